// round 2
// baseline (speedup 1.0000x reference)
#include <cuda_runtime.h>
#include <cuda_bf16.h>
#include <cstdint>

// MultiLevelAlignedRoIPooling: 4-level FPN ROI-Align, P=7, levels 2..5.
// Inputs (metadata order): feat2 (B,256,256,C) f32, feat3 (B,128,128,C),
// feat4 (B,64,64,C), feat5 (B,32,32,C), boxes (B,N,4) f32 [y1,x1,y2,x2].
// Output: (B, N, 7, 7, C) f32.
//
// Strategy: one CTA per (b,n) box. Thread t: channel-quad c4 = t&63
// (C=256 -> 64 float4), cell group g = t>>6 handles cells g, g+4, ...

#define ROIP 7
#define ROIC 256
#define ROIC4 (ROIC / 4)

__global__ __launch_bounds__(256, 4)
void roi_align_kernel(const float* __restrict__ f2,
                      const float* __restrict__ f3,
                      const float* __restrict__ f4,
                      const float* __restrict__ f5,
                      const float* __restrict__ boxes,
                      float* __restrict__ out,
                      int N)
{
    const int bn = blockIdx.x;          // b*N + n
    const int t  = threadIdx.x;

    __shared__ int   sy0[ROIP], sy1[ROIP], sx0[ROIP], sx1[ROIP];
    __shared__ float sly[ROIP], slx[ROIP];
    __shared__ const float* sbase;      // level base for this batch image
    __shared__ int   sW;

    if (t < ROIP) {
        const float y1 = boxes[bn * 4 + 0];
        const float x1 = boxes[bn * 4 + 1];
        const float y2 = boxes[bn * 4 + 2];
        const float x2 = boxes[bn * 4 + 3];
        const float bh = y2 - y1;
        const float bw = x2 - x1;
        const float area_sqrt = sqrtf(bh * bw);
        // lv = clip(floor(ln(a/224)/ln2) + 4, 2, 5)
        int lv = (int)floorf(logf(area_sqrt * (1.0f / 224.0f)) *
                             1.4426950408889634f) + 4;
        lv = lv < 2 ? 2 : (lv > 5 ? 5 : lv);
        const int li = lv - 2;
        const int H  = 256 >> li;       // level extent (== W)
        const float inv = 1.0f / (float)(1 << lv);   // exact power of 2
        const float bnd = (float)(H - 1);

        const float ry0 = y1 * inv - 0.5f;
        const float rx0 = x1 * inv - 0.5f;
        const float rhp = ((y2 * inv - 0.5f) - ry0) * (1.0f / 7.0f);
        const float rwp = ((x2 * inv - 0.5f) - rx0) * (1.0f / 7.0f);

        const int i = t;                // 0..6: one knot per lane
        float gy = fminf(ry0 + (float)i * rhp, bnd);
        float gx = fminf(rx0 + (float)i * rwp, bnd);
        float fy = floorf(gy);
        float fx = floorf(gx);
        int   iy = (int)fy;
        int   ix = (int)fx;
        sy0[i] = iy;
        sx0[i] = ix;
        // The +1 index only leaves the level extent when its bilinear
        // weight is exactly 0 (gy clamped to H-1), so clamping to H-1 is
        // numerically identical to the reference's zero-padded gather.
        sy1[i] = iy + 1 < H ? iy + 1 : H - 1;
        sx1[i] = ix + 1 < H ? ix + 1 : H - 1;
        sly[i] = gy - fy;
        slx[i] = gx - fx;

        if (i == 0) {
            const float* fp = (li == 0) ? f2 : (li == 1) ? f3
                            : (li == 2) ? f4 : f5;
            const int b = bn / N;
            sbase = fp + (size_t)b * (size_t)H * (size_t)H * ROIC;
            sW = H;
        }
    }
    __syncthreads();

    const float4* __restrict__ base = (const float4*)sbase;
    const int W   = sW;
    const int c4  = t & (ROIC4 - 1);
    const int g   = t >> 6;             // 0..3 cell group
    float4* __restrict__ out4 =
        (float4*)(out + (size_t)bn * (ROIP * ROIP * ROIC));

    #pragma unroll 4
    for (int k = 0; k < 13; ++k) {
        const int cell = g + 4 * k;
        if (cell >= ROIP * ROIP) break;
        const int py = cell / ROIP;
        const int px = cell - py * ROIP;

        const int   y0 = sy0[py], y1i = sy1[py];
        const int   x0 = sx0[px], x1i = sx1[px];
        const float ly = sly[py], lx = slx[px];
        const float hy = 1.0f - ly, hx = 1.0f - lx;

        const float w00 = hy * hx, w01 = hy * lx;
        const float w10 = ly * hx, w11 = ly * lx;

        const int r0 = y0  * W;
        const int r1 = y1i * W;
        const float4 v00 = __ldg(base + (r0 + x0 ) * ROIC4 + c4);
        const float4 v01 = __ldg(base + (r0 + x1i) * ROIC4 + c4);
        const float4 v10 = __ldg(base + (r1 + x0 ) * ROIC4 + c4);
        const float4 v11 = __ldg(base + (r1 + x1i) * ROIC4 + c4);

        float4 r;
        r.x = w00 * v00.x + w01 * v01.x + w10 * v10.x + w11 * v11.x;
        r.y = w00 * v00.y + w01 * v01.y + w10 * v10.y + w11 * v11.y;
        r.z = w00 * v00.z + w01 * v01.z + w10 * v10.z + w11 * v11.z;
        r.w = w00 * v00.w + w01 * v01.w + w10 * v10.w + w11 * v11.w;

        out4[cell * ROIC4 + c4] = r;
    }
}

extern "C" void kernel_launch(void* const* d_in, const int* in_sizes, int n_in,
                              void* d_out, int out_size)
{
    const float* f2    = (const float*)d_in[0];
    const float* f3    = (const float*)d_in[1];
    const float* f4    = (const float*)d_in[2];
    const float* f5    = (const float*)d_in[3];
    const float* boxes = (const float*)d_in[4];
    float* out = (float*)d_out;

    // B from feat2: B*256*256*256 elements; N from boxes: B*N*4.
    const int B = in_sizes[0] / (256 * 256 * ROIC);
    const int N = in_sizes[4] / (B * 4);

    roi_align_kernel<<<B * N, 256>>>(f2, f3, f4, f5, boxes, out, N);
}

// round 4
// speedup vs baseline: 1.1333x; 1.1333x over previous
#include <cuda_runtime.h>
#include <cuda_bf16.h>
#include <cstdint>

// MultiLevelAlignedRoIPooling: 4-level FPN ROI-Align, P=7, levels 2..5.
// Inputs: feat2 (B,256,256,C) f32, feat3 (B,128,128,C), feat4 (B,64,64,C),
// feat5 (B,32,32,C), boxes (B,N,4) f32 [y1,x1,y2,x2].
// Output: (B, N, 7, 7, C) f32.
//
// One CTA per (b,n) box. Thread t: channel-quad c4 = t&63, cell group
// g = t>>6. Per-cell gather offsets + bilinear weights are precomputed
// into shared so the main loop is pure LDS/LDG/FFMA/STG.

#define ROIP 7
#define ROIC 256
#define ROIC4 (ROIC / 4)
#define NCELL (ROIP * ROIP)

__global__ __launch_bounds__(256, 4)
void roi_align_kernel(const float* __restrict__ f2,
                      const float* __restrict__ f3,
                      const float* __restrict__ f4,
                      const float* __restrict__ f5,
                      const float* __restrict__ boxes,
                      float* __restrict__ out,
                      int N)
{
    const int bn = blockIdx.x;          // b*N + n
    const int t  = threadIdx.x;

    __shared__ int   sy0[ROIP], sy1[ROIP], sx0[ROIP], sx1[ROIP];
    __shared__ float sly[ROIP], slx[ROIP];
    __shared__ const float* sbase;      // level base for this batch image
    __shared__ int   sW;
    __shared__ int4   soff[NCELL];      // float4-unit offsets of 4 corners
    __shared__ float4 swt[NCELL];       // bilinear weights

    if (t < ROIP) {
        const float y1 = boxes[bn * 4 + 0];
        const float x1 = boxes[bn * 4 + 1];
        const float y2 = boxes[bn * 4 + 2];
        const float x2 = boxes[bn * 4 + 3];
        const float area_sqrt = sqrtf((y2 - y1) * (x2 - x1));
        // lv = clip(floor(ln(a/224)/ln2) + 4, 2, 5)
        int lv = (int)floorf(logf(area_sqrt * (1.0f / 224.0f)) *
                             1.4426950408889634f) + 4;
        lv = lv < 2 ? 2 : (lv > 5 ? 5 : lv);
        const int li = lv - 2;
        const int H  = 256 >> li;       // level extent (== W)
        const float inv = 1.0f / (float)(1 << lv);   // exact power of 2
        const float bnd = (float)(H - 1);

        const float ry0 = y1 * inv - 0.5f;
        const float rx0 = x1 * inv - 0.5f;
        const float rhp = ((y2 * inv - 0.5f) - ry0) * (1.0f / 7.0f);
        const float rwp = ((x2 * inv - 0.5f) - rx0) * (1.0f / 7.0f);

        const int i = t;                // 0..6: one knot per lane
        float gy = fminf(ry0 + (float)i * rhp, bnd);
        float gx = fminf(rx0 + (float)i * rwp, bnd);
        float fy = floorf(gy);
        float fx = floorf(gx);
        int   iy = (int)fy;
        int   ix = (int)fx;
        sy0[i] = iy;
        sx0[i] = ix;
        // The +1 index only leaves the level extent when its bilinear
        // weight is exactly 0 (coord clamped to H-1), so clamping to H-1
        // is numerically identical to the reference's zero-padded gather.
        sy1[i] = iy + 1 < H ? iy + 1 : H - 1;
        sx1[i] = ix + 1 < H ? ix + 1 : H - 1;
        sly[i] = gy - fy;
        slx[i] = gx - fx;

        if (i == 0) {
            const float* fp = (li == 0) ? f2 : (li == 1) ? f3
                            : (li == 2) ? f4 : f5;
            const int b = bn / N;
            sbase = fp + (size_t)b * (size_t)H * (size_t)H * ROIC;
            sW = H;
        }
    }
    __syncthreads();

    if (t < NCELL) {
        const int py = t / ROIP;
        const int px = t - py * ROIP;
        const int W  = sW;
        const int y0 = sy0[py], y1i = sy1[py];
        const int x0 = sx0[px], x1i = sx1[px];
        const float ly = sly[py], lx = slx[px];
        const float hy = 1.0f - ly, hx = 1.0f - lx;
        const int r0 = y0  * W;
        const int r1 = y1i * W;
        soff[t] = make_int4((r0 + x0 ) * ROIC4, (r0 + x1i) * ROIC4,
                            (r1 + x0 ) * ROIC4, (r1 + x1i) * ROIC4);
        swt[t]  = make_float4(hy * hx, hy * lx, ly * hx, ly * lx);
    }
    __syncthreads();

    const int c4 = t & (ROIC4 - 1);
    const int g  = t >> 6;              // 0..3 cell group
    const float4* __restrict__ basec = (const float4*)sbase + c4;
    float4* __restrict__ outc =
        (float4*)(out + (size_t)bn * (NCELL * ROIC)) + c4;

    #pragma unroll
    for (int k = 0; k < 13; ++k) {
        const int cell = g + 4 * k;     // 0..51, uniform per warp
        if (cell < NCELL) {             // compile-time true for k < 12
            const int4   o = soff[cell];
            const float4 w = swt[cell];

            const float4 v00 = __ldg(basec + o.x);
            const float4 v01 = __ldg(basec + o.y);
            const float4 v10 = __ldg(basec + o.z);
            const float4 v11 = __ldg(basec + o.w);

            float4 r;
            r.x = w.x * v00.x + w.y * v01.x + w.z * v10.x + w.w * v11.x;
            r.y = w.x * v00.y + w.y * v01.y + w.z * v10.y + w.w * v11.y;
            r.z = w.x * v00.z + w.y * v01.z + w.z * v10.z + w.w * v11.z;
            r.w = w.x * v00.w + w.y * v01.w + w.z * v10.w + w.w * v11.w;

            __stcs(outc + cell * ROIC4, r);
        }
    }
}

extern "C" void kernel_launch(void* const* d_in, const int* in_sizes, int n_in,
                              void* d_out, int out_size)
{
    const float* f2    = (const float*)d_in[0];
    const float* f3    = (const float*)d_in[1];
    const float* f4    = (const float*)d_in[2];
    const float* f5    = (const float*)d_in[3];
    const float* boxes = (const float*)d_in[4];
    float* out = (float*)d_out;

    const int B = in_sizes[0] / (256 * 256 * ROIC);
    const int N = in_sizes[4] / (B * 4);

    roi_align_kernel<<<B * N, 256>>>(f2, f3, f4, f5, boxes, out, N);
}